// round 1
// baseline (speedup 1.0000x reference)
#include <cuda_runtime.h>
#include <math.h>

#define TT 256
#define BB 128
#define HH 512
#define MM (TT*BB)      // 32768 rows
#define CC 9

// ---------------- scratch (static device globals; no allocs) ----------------
__device__ float g_X0[(size_t)MM*512];        //  64 MB  layer0 input (T,B,512)
__device__ float g_HA[(size_t)MM*1024];       // 128 MB  layer0 output (T,B,1024)
__device__ float g_HB[(size_t)MM*1024];       // 128 MB  layer1 output
__device__ float g_PRE[2ull*MM*2048];         // 512 MB  gate preacts [dir][T*B][2048]
__device__ float g_C[2*BB*HH];                // cell state per dir
__device__ float g_EM[(size_t)MM*CC];         // emissions (T,B,9)
__device__ float g_SC[BB];                    // CRF numerator scores
__device__ float g_LLH[BB];                   // per-batch log-likelihood

__device__ __forceinline__ float sigf(float x){ return 1.0f/(1.0f+expf(-x)); }

// ---------------- embedding lookup + norm clip ----------------
// one block (128 threads) per (t,b) row; float4 per thread (512 dims)
__global__ void embed_kernel(const int* __restrict__ x, const float* __restrict__ embed)
{
    int r = blockIdx.x;            // r = t*BB + b
    int t = r >> 7;
    int b = r & 127;
    int v = x[b*TT + t];
    const float* e = embed + (size_t)v * 512;
    int tid = threadIdx.x;         // 128
    float4 ev = ((const float4*)e)[tid];
    float ss = ev.x*ev.x + ev.y*ev.y + ev.z*ev.z + ev.w*ev.w;
    #pragma unroll
    for (int o = 16; o; o >>= 1) ss += __shfl_xor_sync(0xffffffffu, ss, o);
    __shared__ float sred[4];
    if ((tid & 31) == 0) sred[tid>>5] = ss;
    __syncthreads();
    float nrm = sqrtf(sred[0]+sred[1]+sred[2]+sred[3]);
    float sc = (nrm > 1.0f) ? 1.0f/(nrm + 1e-7f) : 1.0f;
    float4 o4 = make_float4(ev.x*sc, ev.y*sc, ev.z*sc, ev.w*sc);
    ((float4*)(g_X0 + (size_t)r*512))[tid] = o4;
}

// ---------------- input-projection GEMM (both directions fused) ----------------
// C[M=32768, N=4096] = A[M,K] @ W[N,K]^T + bias ; write into g_PRE[dir][m][n&2047]
// 128x128 tile, 256 threads, 8x8 per thread, KC=8
__global__ __launch_bounds__(256, 2) void gemm_pre_kernel(int src, const float* __restrict__ W,
                                                          const float* __restrict__ bias, int K)
{
    const float* A = src ? g_HA : g_X0;
    const int m0 = blockIdx.y << 7;
    const int n0 = blockIdx.x << 7;
    __shared__ float As[8][132];
    __shared__ float Bs[8][132];
    float acc[8][8];
    #pragma unroll
    for (int i=0;i<8;i++)
        #pragma unroll
        for (int j=0;j<8;j++) acc[i][j]=0.f;
    const int tid = threadIdx.x;
    const int lr = tid >> 1;          // 0..127 row within tile
    const int lq = (tid & 1) << 2;    // 0 or 4 (k quad)
    const int ty = tid >> 4;          // 0..15
    const int tx = tid & 15;          // 0..15
    const float* Arow = A + (size_t)(m0 + lr)*K + lq;
    const float* Wrow = W + (size_t)(n0 + lr)*K + lq;

    for (int k0 = 0; k0 < K; k0 += 8) {
        float4 av = *(const float4*)(Arow + k0);
        float4 bv = *(const float4*)(Wrow + k0);
        __syncthreads();
        As[lq+0][lr]=av.x; As[lq+1][lr]=av.y; As[lq+2][lr]=av.z; As[lq+3][lr]=av.w;
        Bs[lq+0][lr]=bv.x; Bs[lq+1][lr]=bv.y; Bs[lq+2][lr]=bv.z; Bs[lq+3][lr]=bv.w;
        __syncthreads();
        #pragma unroll
        for (int kk = 0; kk < 8; kk++) {
            float4 a0 = *(const float4*)&As[kk][ty<<3];
            float4 a1 = *(const float4*)&As[kk][(ty<<3)+4];
            float4 b0 = *(const float4*)&Bs[kk][tx<<3];
            float4 b1 = *(const float4*)&Bs[kk][(tx<<3)+4];
            float aa[8] = {a0.x,a0.y,a0.z,a0.w,a1.x,a1.y,a1.z,a1.w};
            float bb[8] = {b0.x,b0.y,b0.z,b0.w,b1.x,b1.y,b1.z,b1.w};
            #pragma unroll
            for (int i=0;i<8;i++)
                #pragma unroll
                for (int j=0;j<8;j++) acc[i][j] += aa[i]*bb[j];
        }
    }
    #pragma unroll
    for (int i=0;i<8;i++) {
        int m = m0 + (ty<<3) + i;
        #pragma unroll
        for (int j=0;j<8;j++) {
            int n = n0 + (tx<<3) + j;
            int dir = n >> 11;
            int col = n & 2047;
            g_PRE[((size_t)dir*MM + m)*2048 + col] = acc[i][j] + bias[n];
        }
    }
}

// ---------------- one LSTM time step, both directions, fused matmul+gates ----------------
// grid: (jtiles=32, btiles=2, dir=2) = 128 blocks, 256 threads
// block computes z tile 64b x (16 hidden units x 4 gates = 64 w-rows), then gates.
__global__ __launch_bounds__(256) void lstm_step_kernel(const float* __restrict__ Whh,
                                                        int layer, int s)
{
    float* Hbuf = layer ? g_HB : g_HA;
    const int dir = blockIdx.z;
    const int b0  = blockIdx.y << 6;     // 0 or 64
    const int j0  = blockIdx.x << 4;     // 0..496
    const int t_out = dir ? (TT-1-s) : s;
    const int tid = threadIdx.x;
    const int tx = tid & 15, ty = tid >> 4;

    __shared__ float As[8][68];          // h_prev^T tile [k][b_local]
    __shared__ float Ws[8][68];          // Whh^T tile   [k][wrl]
    __shared__ float zbuf[64][65];       // z exchange

    float acc[4][4];
    #pragma unroll
    for (int m=0;m<4;m++)
        #pragma unroll
        for (int n=0;n<4;n++) acc[m][n]=0.f;

    if (s > 0) {
        const int prev_row = dir ? (t_out + 1) : (s - 1);
        const float* hprev = Hbuf + (size_t)prev_row*BB*1024 + (size_t)dir*512;
        const float* wbase = Whh + (size_t)dir*2048*512;
        const int lr = tid >> 2;           // 0..63
        const int lk = (tid & 3) << 1;     // 0,2,4,6
        const int wrow = (lr >> 4)*512 + j0 + (lr & 15);   // gate*512 + j
        const float* hp = hprev + (size_t)(b0 + lr)*1024 + lk;
        const float* wp = wbase + (size_t)wrow*512 + lk;

        for (int k0 = 0; k0 < 512; k0 += 8) {
            float2 hv = *(const float2*)(hp + k0);
            float2 wv = *(const float2*)(wp + k0);
            __syncthreads();
            As[lk][lr]=hv.x; As[lk+1][lr]=hv.y;
            Ws[lk][lr]=wv.x; Ws[lk+1][lr]=wv.y;
            __syncthreads();
            #pragma unroll
            for (int kk=0;kk<8;kk++) {
                float4 w4 = *(const float4*)&Ws[kk][tx<<2];
                float a0 = As[kk][ty];
                float a1 = As[kk][ty+16];
                float a2 = As[kk][ty+32];
                float a3 = As[kk][ty+48];
                acc[0][0]+=a0*w4.x; acc[0][1]+=a0*w4.y; acc[0][2]+=a0*w4.z; acc[0][3]+=a0*w4.w;
                acc[1][0]+=a1*w4.x; acc[1][1]+=a1*w4.y; acc[1][2]+=a1*w4.z; acc[1][3]+=a1*w4.w;
                acc[2][0]+=a2*w4.x; acc[2][1]+=a2*w4.y; acc[2][2]+=a2*w4.z; acc[2][3]+=a2*w4.w;
                acc[3][0]+=a3*w4.x; acc[3][1]+=a3*w4.y; acc[3][2]+=a3*w4.z; acc[3][3]+=a3*w4.w;
            }
        }
    }
    __syncthreads();
    #pragma unroll
    for (int m=0;m<4;m++)
        #pragma unroll
        for (int n=0;n<4;n++) zbuf[ty + (m<<4)][(tx<<2)+n] = acc[m][n];
    __syncthreads();

    const float* prer = g_PRE + ((size_t)dir*MM + (size_t)t_out*BB)*2048;
    #pragma unroll
    for (int q=0;q<4;q++) {
        int idx = tid + (q<<8);          // 0..1023
        int bl = idx >> 4, jl = idx & 15;
        int b = b0 + bl, j = j0 + jl;
        const float* pr = prer + (size_t)b*2048 + j;
        float zi = zbuf[bl][jl]       + pr[0];
        float zf = zbuf[bl][jl+16]    + pr[512];
        float zg = zbuf[bl][jl+32]    + pr[1024];
        float zo = zbuf[bl][jl+48]    + pr[1536];
        float* cp = &g_C[((dir<<7) + b)*512 + j];
        float cprev = (s > 0) ? *cp : 0.f;
        float fi = sigf(zi), ff = sigf(zf), fg = tanhf(zg), fo = sigf(zo);
        float c = ff*cprev + fi*fg;
        float h = fo*tanhf(c);
        *cp = c;
        Hbuf[((size_t)t_out*BB + b)*1024 + (dir<<9) + j] = h;
    }
}

// ---------------- classifier emissions: (T*B,1024) @ (9,1024)^T + b ----------------
__global__ void emissions_kernel(const float* __restrict__ clsW, const float* __restrict__ clsB)
{
    int warp = threadIdx.x >> 5, lane = threadIdx.x & 31;
    int row = (blockIdx.x << 3) + warp;   // 0..32767
    const float* h = g_HB + (size_t)row * 1024;
    float hv[32];
    #pragma unroll
    for (int m=0;m<32;m++) hv[m] = h[lane + (m<<5)];
    #pragma unroll
    for (int c=0;c<CC;c++) {
        const float* w = clsW + c*1024;
        float s = 0.f;
        #pragma unroll
        for (int m=0;m<32;m++) s += hv[m]*w[lane + (m<<5)];
        #pragma unroll
        for (int o=16;o;o>>=1) s += __shfl_xor_sync(0xffffffffu, s, o);
        if (lane==0) g_EM[(size_t)row*CC + c] = s + clsB[c];
    }
}

// ---------------- CRF numerator (one thread per batch) ----------------
__global__ void crf_num_kernel(const int* __restrict__ y, const float* __restrict__ trans,
                               const float* __restrict__ cstart, const float* __restrict__ cend)
{
    int b = threadIdx.x;  // 128
    int y0 = y[b*TT];
    int tg = y0 > 0 ? y0 : 0;
    float sc = cstart[tg] + g_EM[(size_t)b*CC + tg];
    int cnt = (y0 > -1) ? 1 : 0;
    int prev = tg;
    for (int t=1;t<TT;t++) {
        int yt = y[b*TT + t];
        int tgt = yt > 0 ? yt : 0;
        float mf = (yt > -1) ? 1.f : 0.f;
        sc += (trans[prev*CC + tgt] + g_EM[((size_t)t*BB + b)*CC + tgt]) * mf;
        prev = tgt;
        cnt += (yt > -1) ? 1 : 0;
    }
    int se = cnt - 1; if (se < 0) se = 0;
    int yl = y[b*TT + se];
    int lt = yl > 0 ? yl : 0;
    sc += cend[lt];
    g_SC[b] = sc;
}

// ---------------- CRF denominator (forward algorithm), one warp per batch ----------------
__global__ void crf_den_kernel(const int* __restrict__ y, const float* __restrict__ trans,
                               const float* __restrict__ cstart, const float* __restrict__ cend)
{
    int b = (blockIdx.x << 3) + (threadIdx.x >> 5);
    int lane = threadIdx.x & 31;
    int c = lane < CC ? lane : CC-1;
    float tcol[CC];
    #pragma unroll
    for (int i=0;i<CC;i++) tcol[i] = trans[i*CC + c];
    float alpha = cstart[c] + g_EM[(size_t)b*CC + c];
    for (int t=1;t<TT;t++) {
        float e = g_EM[((size_t)t*BB + b)*CC + c];
        float av[CC]; float mx = -1e30f;
        #pragma unroll
        for (int i=0;i<CC;i++) { av[i] = __shfl_sync(0xffffffffu, alpha, i) + tcol[i]; mx = fmaxf(mx, av[i]); }
        float su = 0.f;
        #pragma unroll
        for (int i=0;i<CC;i++) su += expf(av[i]-mx);
        float nxt = mx + logf(su) + e;
        if (y[b*TT + t] > -1) alpha = nxt;
    }
    float v = alpha + cend[c];
    float mx = -1e30f;
    #pragma unroll
    for (int i=0;i<CC;i++) mx = fmaxf(mx, __shfl_sync(0xffffffffu, v, i));
    float su = 0.f;
    #pragma unroll
    for (int i=0;i<CC;i++) su += expf(__shfl_sync(0xffffffffu, v, i) - mx);
    if (lane==0) g_LLH[b] = g_SC[b] - (mx + logf(su));
}

// ---------------- final reduction: -mean(llh) ----------------
__global__ void final_kernel(float* __restrict__ out)
{
    int tid = threadIdx.x; // 128
    float v = g_LLH[tid];
    #pragma unroll
    for (int o=16;o;o>>=1) v += __shfl_xor_sync(0xffffffffu, v, o);
    __shared__ float sr[4];
    if ((tid&31)==0) sr[tid>>5] = v;
    __syncthreads();
    if (tid==0) out[0] = -(sr[0]+sr[1]+sr[2]+sr[3]) / 128.0f;
}

// ---------------- launch ----------------
extern "C" void kernel_launch(void* const* d_in, const int* in_sizes, int n_in,
                              void* d_out, int out_size)
{
    const int*   x        = (const int*)  d_in[0];   // (B,T)
    const int*   y        = (const int*)  d_in[1];   // (B,T)
    const float* embed    = (const float*)d_in[2];   // (30000,512)
    const float* w_ih_l0  = (const float*)d_in[3];   // (2,2048,512) -> (4096,512)
    const float* w_hh_l0  = (const float*)d_in[4];   // (2,2048,512)
    const float* b_l0     = (const float*)d_in[5];   // (4096)
    const float* w_ih_l1  = (const float*)d_in[6];   // (2,2048,1024) -> (4096,1024)
    const float* w_hh_l1  = (const float*)d_in[7];   // (2,2048,512)
    const float* b_l1     = (const float*)d_in[8];   // (4096)
    const float* cls_w    = (const float*)d_in[9];   // (9,1024)
    const float* cls_b    = (const float*)d_in[10];  // (9)
    const float* crf_start= (const float*)d_in[11];  // (9)
    const float* crf_end  = (const float*)d_in[12];  // (9)
    const float* crf_trans= (const float*)d_in[13];  // (9,9)
    float* out = (float*)d_out;

    // 1) embedding + norm clip -> g_X0 (T,B,512)
    embed_kernel<<<MM, 128>>>(x, embed);

    // 2) layer0 input projection (both dirs) -> g_PRE
    gemm_pre_kernel<<<dim3(32,256), 256>>>(0, w_ih_l0, b_l0, 512);

    // 3) layer0 scan (fwd+bwd concurrently per step) -> g_HA
    for (int s = 0; s < TT; s++)
        lstm_step_kernel<<<dim3(32,2,2), 256>>>(w_hh_l0, 0, s);

    // 4) layer1 input projection from g_HA -> g_PRE
    gemm_pre_kernel<<<dim3(32,256), 256>>>(1, w_ih_l1, b_l1, 1024);

    // 5) layer1 scan -> g_HB
    for (int s = 0; s < TT; s++)
        lstm_step_kernel<<<dim3(32,2,2), 256>>>(w_hh_l1, 1, s);

    // 6) emissions
    emissions_kernel<<<4096, 256>>>(cls_w, cls_b);

    // 7) CRF numerator + denominator + final loss
    crf_num_kernel<<<1, 128>>>(y, crf_trans, crf_start, crf_end);
    crf_den_kernel<<<16, 256>>>(y, crf_trans, crf_start, crf_end);
    final_kernel<<<1, 128>>>(out);
}

// round 2
// speedup vs baseline: 1.9782x; 1.9782x over previous
#include <cuda_runtime.h>
#include <math.h>

#define TT 256
#define BB 128
#define HH 512
#define MM (TT*BB)      // 32768 rows
#define CC 9

// ---------------- scratch (static device globals; no allocs) ----------------
__device__ float g_X0[(size_t)MM*512];        //  64 MB  layer0 input (T,B,512)
__device__ float g_HA[(size_t)MM*1024];       // 128 MB  layer0 output (T,B,1024)
__device__ float g_HB[(size_t)MM*1024];       // 128 MB  layer1 output
__device__ float g_PRE[2ull*MM*2048];         // 512 MB  gate preacts [dir][T*B][2048]
__device__ float g_C[2*BB*HH];                // cell state per dir
__device__ float g_EM[(size_t)MM*CC];         // emissions (T,B,9)
__device__ float g_SC[BB];                    // CRF numerator scores
__device__ float g_LLH[BB];                   // per-batch log-likelihood
__device__ unsigned g_bar_arrive = 0;         // software grid barrier
__device__ unsigned g_bar_gen = 0;

__device__ __forceinline__ float sigf(float x){ return 1.0f/(1.0f+expf(-x)); }

// ---------------- embedding lookup + norm clip ----------------
__global__ void embed_kernel(const int* __restrict__ x, const float* __restrict__ embed)
{
    int r = blockIdx.x;            // r = t*BB + b
    int t = r >> 7;
    int b = r & 127;
    int v = x[b*TT + t];
    const float* e = embed + (size_t)v * 512;
    int tid = threadIdx.x;         // 128
    float4 ev = ((const float4*)e)[tid];
    float ss = ev.x*ev.x + ev.y*ev.y + ev.z*ev.z + ev.w*ev.w;
    #pragma unroll
    for (int o = 16; o; o >>= 1) ss += __shfl_xor_sync(0xffffffffu, ss, o);
    __shared__ float sred[4];
    if ((tid & 31) == 0) sred[tid>>5] = ss;
    __syncthreads();
    float nrm = sqrtf(sred[0]+sred[1]+sred[2]+sred[3]);
    float sc = (nrm > 1.0f) ? 1.0f/(nrm + 1e-7f) : 1.0f;
    float4 o4 = make_float4(ev.x*sc, ev.y*sc, ev.z*sc, ev.w*sc);
    ((float4*)(g_X0 + (size_t)r*512))[tid] = o4;
}

// ---------------- input-projection GEMM (both directions fused) ----------------
__global__ __launch_bounds__(256, 2) void gemm_pre_kernel(int src, const float* __restrict__ W,
                                                          const float* __restrict__ bias, int K)
{
    const float* A = src ? g_HA : g_X0;
    const int m0 = blockIdx.y << 7;
    const int n0 = blockIdx.x << 7;
    __shared__ float As[8][132];
    __shared__ float Bs[8][132];
    float acc[8][8];
    #pragma unroll
    for (int i=0;i<8;i++)
        #pragma unroll
        for (int j=0;j<8;j++) acc[i][j]=0.f;
    const int tid = threadIdx.x;
    const int lr = tid >> 1;
    const int lq = (tid & 1) << 2;
    const int ty = tid >> 4;
    const int tx = tid & 15;
    const float* Arow = A + (size_t)(m0 + lr)*K + lq;
    const float* Wrow = W + (size_t)(n0 + lr)*K + lq;

    for (int k0 = 0; k0 < K; k0 += 8) {
        float4 av = *(const float4*)(Arow + k0);
        float4 bv = *(const float4*)(Wrow + k0);
        __syncthreads();
        As[lq+0][lr]=av.x; As[lq+1][lr]=av.y; As[lq+2][lr]=av.z; As[lq+3][lr]=av.w;
        Bs[lq+0][lr]=bv.x; Bs[lq+1][lr]=bv.y; Bs[lq+2][lr]=bv.z; Bs[lq+3][lr]=bv.w;
        __syncthreads();
        #pragma unroll
        for (int kk = 0; kk < 8; kk++) {
            float4 a0 = *(const float4*)&As[kk][ty<<3];
            float4 a1 = *(const float4*)&As[kk][(ty<<3)+4];
            float4 b0 = *(const float4*)&Bs[kk][tx<<3];
            float4 b1 = *(const float4*)&Bs[kk][(tx<<3)+4];
            float aa[8] = {a0.x,a0.y,a0.z,a0.w,a1.x,a1.y,a1.z,a1.w};
            float bb[8] = {b0.x,b0.y,b0.z,b0.w,b1.x,b1.y,b1.z,b1.w};
            #pragma unroll
            for (int i=0;i<8;i++)
                #pragma unroll
                for (int j=0;j<8;j++) acc[i][j] += aa[i]*bb[j];
        }
    }
    #pragma unroll
    for (int i=0;i<8;i++) {
        int m = m0 + (ty<<3) + i;
        #pragma unroll
        for (int j=0;j<8;j++) {
            int n = n0 + (tx<<3) + j;
            int dir = n >> 11;
            int col = n & 2047;
            g_PRE[((size_t)dir*MM + m)*2048 + col] = acc[i][j] + bias[n];
        }
    }
}

// ---------------- persistent LSTM scan: one launch per layer ----------------
// grid = 128 blocks (1/SM), 256 threads. Block owns (dir, b-half, 16 hidden units).
// Whh slice (64 rows x 512) lives in SMEM for all 256 steps. Steps separated by
// a software grid barrier (all 128 blocks co-resident: 152KB smem -> 1 block/SM).
__global__ __launch_bounds__(256, 1) void lstm_scan_kernel(const float* __restrict__ Whh, int layer)
{
    extern __shared__ float sm[];
    float* Ws = sm;                    // [512][64]
    float* As = sm + 512*64;           // [16][68]
    float* zb = As + 16*68;            // [64][65]

    float* Hbuf = layer ? g_HB : g_HA;
    const int bid = blockIdx.x;
    const int dir = bid >> 6;
    const int rem = bid & 63;
    const int b0  = (rem >> 5) << 6;   // 0 or 64
    const int j0  = (rem & 31) << 4;   // 0..496
    const int tid = threadIdx.x;
    const int tx = tid & 15, ty = tid >> 4;
    const int lr = tid >> 2;           // 0..63
    const int lk = (tid & 3) << 2;     // 0,4,8,12

    // ---- load Whh slice into SMEM once (transposed: Ws[k][wr]) ----
    {
        const float* wbase = Whh + (size_t)dir*2048*512;
        int wr = tid >> 2;
        int kq = (tid & 3) << 2;
        int wrow = ((wr >> 4) << 9) + j0 + (wr & 15);   // gate*512 + j
        const float* wp = wbase + (size_t)wrow*512;
        for (int k = kq; k < 512; k += 16) {
            float4 w = *(const float4*)(wp + k);
            Ws[(k+0)*64 + wr] = w.x;
            Ws[(k+1)*64 + wr] = w.y;
            Ws[(k+2)*64 + wr] = w.z;
            Ws[(k+3)*64 + wr] = w.w;
        }
    }
    unsigned bar_target = *(volatile unsigned*)&g_bar_gen;   // stable until our first arrive
    __syncthreads();

    for (int s = 0; s < TT; s++) {
        const int t_out = dir ? (TT-1-s) : s;
        float acc[4][4];
        #pragma unroll
        for (int m=0;m<4;m++)
            #pragma unroll
            for (int n=0;n<4;n++) acc[m][n]=0.f;

        if (s > 0) {
            const int t_prev = dir ? (t_out + 1) : (s - 1);
            const float* hp = Hbuf + ((size_t)t_prev*BB + b0 + lr)*1024 + (dir<<9) + lk;
            float4 hv = __ldcg((const float4*)hp);
            for (int k0 = 0; k0 < 512; k0 += 16) {
                __syncthreads();
                As[(lk+0)*68 + lr] = hv.x;
                As[(lk+1)*68 + lr] = hv.y;
                As[(lk+2)*68 + lr] = hv.z;
                As[(lk+3)*68 + lr] = hv.w;
                __syncthreads();
                if (k0 + 16 < 512) hv = __ldcg((const float4*)(hp + k0 + 16));
                #pragma unroll
                for (int kk = 0; kk < 16; kk++) {
                    float4 w4 = *(const float4*)&Ws[(k0+kk)*64 + (tx<<2)];
                    float a0 = As[kk*68 + ty];
                    float a1 = As[kk*68 + ty + 16];
                    float a2 = As[kk*68 + ty + 32];
                    float a3 = As[kk*68 + ty + 48];
                    acc[0][0]+=a0*w4.x; acc[0][1]+=a0*w4.y; acc[0][2]+=a0*w4.z; acc[0][3]+=a0*w4.w;
                    acc[1][0]+=a1*w4.x; acc[1][1]+=a1*w4.y; acc[1][2]+=a1*w4.z; acc[1][3]+=a1*w4.w;
                    acc[2][0]+=a2*w4.x; acc[2][1]+=a2*w4.y; acc[2][2]+=a2*w4.z; acc[2][3]+=a2*w4.w;
                    acc[3][0]+=a3*w4.x; acc[3][1]+=a3*w4.y; acc[3][2]+=a3*w4.z; acc[3][3]+=a3*w4.w;
                }
            }
        }
        __syncthreads();
        #pragma unroll
        for (int m=0;m<4;m++)
            #pragma unroll
            for (int n=0;n<4;n++) zb[(ty + (m<<4))*65 + (tx<<2) + n] = acc[m][n];
        __syncthreads();

        // ---- gates + state update ----
        const float* prer = g_PRE + ((size_t)dir*MM + (size_t)t_out*BB)*2048;
        #pragma unroll
        for (int q=0;q<4;q++) {
            int idx = tid + (q<<8);
            int bl = idx >> 4, jl = idx & 15;
            int b = b0 + bl, j = j0 + jl;
            const float* pr = prer + (size_t)b*2048 + j;
            float zi = zb[bl*65 + jl]      + pr[0];
            float zf = zb[bl*65 + jl + 16] + pr[512];
            float zg = zb[bl*65 + jl + 32] + pr[1024];
            float zo = zb[bl*65 + jl + 48] + pr[1536];
            float* cp = &g_C[((dir<<7) + b)*512 + j];
            float cprev = (s > 0) ? *cp : 0.f;
            float fi = sigf(zi), ff = sigf(zf), fg = tanhf(zg), fo = sigf(zo);
            float c = ff*cprev + fi*fg;
            float h = fo*tanhf(c);
            *cp = c;
            Hbuf[((size_t)t_out*BB + b)*1024 + (dir<<9) + j] = h;
        }

        // ---- grid barrier ----
        bar_target++;
        __syncthreads();
        if (tid == 0) {
            __threadfence();
            unsigned old = atomicAdd(&g_bar_arrive, 1u);
            if (old == 127u) {
                g_bar_arrive = 0u;
                __threadfence();
                atomicAdd(&g_bar_gen, 1u);
            } else {
                while (atomicAdd(&g_bar_gen, 0u) < bar_target) { __nanosleep(32); }
            }
            __threadfence();
        }
        __syncthreads();
    }
}

// ---------------- classifier emissions: (T*B,1024) @ (9,1024)^T + b ----------------
__global__ void emissions_kernel(const float* __restrict__ clsW, const float* __restrict__ clsB)
{
    int warp = threadIdx.x >> 5, lane = threadIdx.x & 31;
    int row = (blockIdx.x << 3) + warp;
    const float* h = g_HB + (size_t)row * 1024;
    float hv[32];
    #pragma unroll
    for (int m=0;m<32;m++) hv[m] = h[lane + (m<<5)];
    #pragma unroll
    for (int c=0;c<CC;c++) {
        const float* w = clsW + c*1024;
        float s = 0.f;
        #pragma unroll
        for (int m=0;m<32;m++) s += hv[m]*w[lane + (m<<5)];
        #pragma unroll
        for (int o=16;o;o>>=1) s += __shfl_xor_sync(0xffffffffu, s, o);
        if (lane==0) g_EM[(size_t)row*CC + c] = s + clsB[c];
    }
}

// ---------------- CRF numerator ----------------
__global__ void crf_num_kernel(const int* __restrict__ y, const float* __restrict__ trans,
                               const float* __restrict__ cstart, const float* __restrict__ cend)
{
    int b = threadIdx.x;
    int y0 = y[b*TT];
    int tg = y0 > 0 ? y0 : 0;
    float sc = cstart[tg] + g_EM[(size_t)b*CC + tg];
    int cnt = (y0 > -1) ? 1 : 0;
    int prev = tg;
    for (int t=1;t<TT;t++) {
        int yt = y[b*TT + t];
        int tgt = yt > 0 ? yt : 0;
        float mf = (yt > -1) ? 1.f : 0.f;
        sc += (trans[prev*CC + tgt] + g_EM[((size_t)t*BB + b)*CC + tgt]) * mf;
        prev = tgt;
        cnt += (yt > -1) ? 1 : 0;
    }
    int se = cnt - 1; if (se < 0) se = 0;
    int yl = y[b*TT + se];
    int lt = yl > 0 ? yl : 0;
    sc += cend[lt];
    g_SC[b] = sc;
}

// ---------------- CRF denominator ----------------
__global__ void crf_den_kernel(const int* __restrict__ y, const float* __restrict__ trans,
                               const float* __restrict__ cstart, const float* __restrict__ cend)
{
    int b = (blockIdx.x << 3) + (threadIdx.x >> 5);
    int lane = threadIdx.x & 31;
    int c = lane < CC ? lane : CC-1;
    float tcol[CC];
    #pragma unroll
    for (int i=0;i<CC;i++) tcol[i] = trans[i*CC + c];
    float alpha = cstart[c] + g_EM[(size_t)b*CC + c];
    for (int t=1;t<TT;t++) {
        float e = g_EM[((size_t)t*BB + b)*CC + c];
        float av[CC]; float mx = -1e30f;
        #pragma unroll
        for (int i=0;i<CC;i++) { av[i] = __shfl_sync(0xffffffffu, alpha, i) + tcol[i]; mx = fmaxf(mx, av[i]); }
        float su = 0.f;
        #pragma unroll
        for (int i=0;i<CC;i++) su += expf(av[i]-mx);
        float nxt = mx + logf(su) + e;
        if (y[b*TT + t] > -1) alpha = nxt;
    }
    float v = alpha + cend[c];
    float mx = -1e30f;
    #pragma unroll
    for (int i=0;i<CC;i++) mx = fmaxf(mx, __shfl_sync(0xffffffffu, v, i));
    float su = 0.f;
    #pragma unroll
    for (int i=0;i<CC;i++) su += expf(__shfl_sync(0xffffffffu, v, i) - mx);
    if (lane==0) g_LLH[b] = g_SC[b] - (mx + logf(su));
}

// ---------------- final reduction ----------------
__global__ void final_kernel(float* __restrict__ out)
{
    int tid = threadIdx.x;
    float v = g_LLH[tid];
    #pragma unroll
    for (int o=16;o;o>>=1) v += __shfl_xor_sync(0xffffffffu, v, o);
    __shared__ float sr[4];
    if ((tid&31)==0) sr[tid>>5] = v;
    __syncthreads();
    if (tid==0) out[0] = -(sr[0]+sr[1]+sr[2]+sr[3]) / 128.0f;
}

// ---------------- launch ----------------
extern "C" void kernel_launch(void* const* d_in, const int* in_sizes, int n_in,
                              void* d_out, int out_size)
{
    const int*   x        = (const int*)  d_in[0];
    const int*   y        = (const int*)  d_in[1];
    const float* embed    = (const float*)d_in[2];
    const float* w_ih_l0  = (const float*)d_in[3];
    const float* w_hh_l0  = (const float*)d_in[4];
    const float* b_l0     = (const float*)d_in[5];
    const float* w_ih_l1  = (const float*)d_in[6];
    const float* w_hh_l1  = (const float*)d_in[7];
    const float* b_l1     = (const float*)d_in[8];
    const float* cls_w    = (const float*)d_in[9];
    const float* cls_b    = (const float*)d_in[10];
    const float* crf_start= (const float*)d_in[11];
    const float* crf_end  = (const float*)d_in[12];
    const float* crf_trans= (const float*)d_in[13];
    float* out = (float*)d_out;

    const int SCAN_SMEM = (512*64 + 16*68 + 64*65) * 4;   // 152064 B
    cudaFuncSetAttribute(lstm_scan_kernel, cudaFuncAttributeMaxDynamicSharedMemorySize, SCAN_SMEM);

    embed_kernel<<<MM, 128>>>(x, embed);
    gemm_pre_kernel<<<dim3(32,256), 256>>>(0, w_ih_l0, b_l0, 512);
    lstm_scan_kernel<<<128, 256, SCAN_SMEM>>>(w_hh_l0, 0);
    gemm_pre_kernel<<<dim3(32,256), 256>>>(1, w_ih_l1, b_l1, 1024);
    lstm_scan_kernel<<<128, 256, SCAN_SMEM>>>(w_hh_l1, 1);
    emissions_kernel<<<4096, 256>>>(cls_w, cls_b);
    crf_num_kernel<<<1, 128>>>(y, crf_trans, crf_start, crf_end);
    crf_den_kernel<<<16, 256>>>(y, crf_trans, crf_start, crf_end);
    final_kernel<<<1, 128>>>(out);
}

// round 3
// speedup vs baseline: 5.4385x; 2.7492x over previous
#include <cuda_runtime.h>
#include <cuda_bf16.h>
#include <math.h>

#define TT 256
#define BB 128
#define CC 9
#define MM (TT*BB)      // 32768 rows

typedef __nv_bfloat16 bf16;

// ---------------- scratch (static device globals; no allocs) ----------------
__device__ bf16  g_X0b[(size_t)MM*512];       // layer0 input, bf16 (T,B,512)
__device__ bf16  g_HAb[(size_t)MM*1024];      // layer0 h, bf16 (T,B,1024)
__device__ bf16  g_HBb[(size_t)MM*1024];      // layer1 h, bf16
__device__ float g_PRE[2ull*MM*2048];         // gate preacts fp32 [dir][T*B][2048]
__device__ float g_C[2*BB*512];               // cell state fp32
__device__ bf16  g_WI0b[4096*512];            // w_ih_l0 bf16
__device__ bf16  g_WI1b[(size_t)4096*1024];   // w_ih_l1 bf16
__device__ bf16  g_WH0b[2*2048*512];          // w_hh_l0 bf16
__device__ bf16  g_WH1b[2*2048*512];          // w_hh_l1 bf16
__device__ float g_EM[(size_t)MM*CC];
__device__ float g_SC[BB];
__device__ float g_LLH[BB];
__device__ unsigned g_bar_arrive = 0;
__device__ unsigned g_bar_gen = 0;

__device__ __forceinline__ float sigf(float x){ return 1.0f/(1.0f+expf(-x)); }

// ---------------- PTX helpers ----------------
__device__ __forceinline__ unsigned su32(const void* p){ return (unsigned)__cvta_generic_to_shared(p); }
__device__ __forceinline__ void cp16(unsigned s, const void* g){
    asm volatile("cp.async.cg.shared.global [%0], [%1], 16;\n" :: "r"(s), "l"(g));
}
__device__ __forceinline__ void cpcommit(){ asm volatile("cp.async.commit_group;\n"); }
template<int N> __device__ __forceinline__ void cpwait(){ asm volatile("cp.async.wait_group %0;\n"::"n"(N)); }
__device__ __forceinline__ void ldsm4(unsigned &r0, unsigned &r1, unsigned &r2, unsigned &r3, unsigned addr){
    asm volatile("ldmatrix.sync.aligned.m8n8.x4.shared.b16 {%0,%1,%2,%3}, [%4];\n"
        : "=r"(r0),"=r"(r1),"=r"(r2),"=r"(r3) : "r"(addr));
}
__device__ __forceinline__ void mma16816(float* c, const unsigned* a, unsigned b0, unsigned b1){
    asm volatile("mma.sync.aligned.m16n8k16.row.col.f32.bf16.bf16.f32 "
        "{%0,%1,%2,%3}, {%4,%5,%6,%7}, {%8,%9}, {%0,%1,%2,%3};\n"
        : "+f"(c[0]),"+f"(c[1]),"+f"(c[2]),"+f"(c[3])
        : "r"(a[0]),"r"(a[1]),"r"(a[2]),"r"(a[3]),"r"(b0),"r"(b1));
}

__device__ __forceinline__ void grid_barrier(unsigned target){
    __syncthreads();
    if (threadIdx.x==0){
        __threadfence();
        unsigned old = atomicAdd(&g_bar_arrive,1u);
        if (old==127u){ g_bar_arrive=0u; __threadfence(); atomicAdd(&g_bar_gen,1u); }
        else { while (atomicAdd(&g_bar_gen,0u) < target) __nanosleep(32); }
        __threadfence();
    }
    __syncthreads();
}

// ---------------- embedding lookup + norm clip -> bf16 ----------------
__global__ void embed_kernel(const int* __restrict__ x, const float* __restrict__ embed)
{
    int r = blockIdx.x;            // r = t*BB + b
    int t = r >> 7;
    int b = r & 127;
    int v = x[b*TT + t];
    const float* e = embed + (size_t)v * 512;
    int tid = threadIdx.x;         // 128
    float4 ev = ((const float4*)e)[tid];
    float ss = ev.x*ev.x + ev.y*ev.y + ev.z*ev.z + ev.w*ev.w;
    #pragma unroll
    for (int o = 16; o; o >>= 1) ss += __shfl_xor_sync(0xffffffffu, ss, o);
    __shared__ float sred[4];
    if ((tid & 31) == 0) sred[tid>>5] = ss;
    __syncthreads();
    float nrm = sqrtf(sred[0]+sred[1]+sred[2]+sred[3]);
    float sc = (nrm > 1.0f) ? 1.0f/(nrm + 1e-7f) : 1.0f;
    __nv_bfloat162 p0 = __floats2bfloat162_rn(ev.x*sc, ev.y*sc);
    __nv_bfloat162 p1 = __floats2bfloat162_rn(ev.z*sc, ev.w*sc);
    __nv_bfloat162* op = (__nv_bfloat162*)(g_X0b + (size_t)r*512);
    op[tid*2]   = p0;
    op[tid*2+1] = p1;
}

// ---------------- weight fp32 -> bf16 conversion ----------------
__global__ void convert_weights(const float* __restrict__ wi0, const float* __restrict__ wh0,
                                const float* __restrict__ wi1, const float* __restrict__ wh1)
{
    const int N0 = 2*2048*512;      // wi0
    const int N1 = 2*2048*512;      // wh0
    const int N2 = 2*2048*1024;     // wi1
    const int N3 = 2*2048*512;      // wh1
    int total = N0+N1+N2+N3;
    for (int i = blockIdx.x*blockDim.x + threadIdx.x; i < total; i += gridDim.x*blockDim.x) {
        if (i < N0)                    g_WI0b[i] = __float2bfloat16(wi0[i]);
        else if (i < N0+N1)            g_WH0b[i-N0] = __float2bfloat16(wh0[i-N0]);
        else if (i < N0+N1+N2)         g_WI1b[i-N0-N1] = __float2bfloat16(wi1[i-N0-N1]);
        else                           g_WH1b[i-N0-N1-N2] = __float2bfloat16(wh1[i-N0-N1-N2]);
    }
}

// ---------------- bf16 tensor-core input-projection GEMM ----------------
// C[32768, 4096] = A[M,K]bf16 @ W[N,K]bf16^T + bias, fp32 out to g_PRE[dir][m][n&2047]
// BM=128 BN=128 BK=64, 8 warps (2m x 4n), warp tile 64x32, double-buffered cp.async
__global__ __launch_bounds__(256) void gemm_pre_mma(int layer, const float* __restrict__ bias)
{
    const bf16* A = layer ? g_HAb : g_X0b;
    const bf16* W = layer ? g_WI1b : g_WI0b;
    const int K  = layer ? 1024 : 512;
    const int m0 = blockIdx.y << 7;
    const int n0 = blockIdx.x << 7;

    extern __shared__ char smraw[];
    bf16* As = (bf16*)smraw;            // 2 stages x [128][64]
    bf16* Bs = As + 2*128*64;           // 2 stages x [128][64]
    unsigned AsB = su32(As), BsB = su32(Bs);

    const int tid = threadIdx.x;
    const int warp = tid>>5, lane = tid&31;
    const int wm = warp>>2, wn = warp&3;

    float acc[4][4][4];
    #pragma unroll
    for (int i=0;i<4;i++)
        #pragma unroll
        for (int j=0;j<4;j++)
            #pragma unroll
            for (int k=0;k<4;k++) acc[i][j][k]=0.f;

    // staging: thread t -> row = t>>1, chunks (t&1)*4 .. +3  (chunk = 8 bf16 = 16B)
    const int srow = tid>>1;
    const int skc0 = (tid&1)*4;
    const bf16* Ag = A + (size_t)(m0+srow)*K + skc0*8;
    const bf16* Wg = W + (size_t)(n0+srow)*K + skc0*8;
    unsigned AsRow = AsB + srow*128;
    unsigned BsRow = BsB + srow*128;

    const int iters = K >> 6;
    // preload stage 0
    #pragma unroll
    for (int i=0;i<4;i++){
        int kc = skc0+i;
        unsigned sw = ((kc ^ (srow&7))<<4);
        cp16(AsRow + sw, Ag + i*8);
        cp16(BsRow + sw, Wg + i*8);
    }
    cpcommit();

    for (int kt=0; kt<iters; kt++){
        int s = kt&1;
        if (kt+1 < iters){
            int koff = (kt+1)<<6;
            #pragma unroll
            for (int i=0;i<4;i++){
                int kc = skc0+i;
                unsigned sw = ((s^1)*128*128) + ((kc ^ (srow&7))<<4);
                cp16(AsRow + sw, Ag + koff + i*8);
                cp16(BsRow + sw, Wg + koff + i*8);
            }
            cpcommit();
            cpwait<1>();
        } else {
            cpwait<0>();
        }
        __syncthreads();

        unsigned Ab = AsB + s*128*128;
        unsigned Bb = BsB + s*128*128;
        #pragma unroll
        for (int kk=0; kk<4; kk++){
            unsigned af[4][4];
            #pragma unroll
            for (int mt=0; mt<4; mt++){
                int row = wm*64 + mt*16 + (lane&7) + ((lane>>3)&1)*8;
                int ch  = kk*2 + (lane>>4);
                ldsm4(af[mt][0],af[mt][1],af[mt][2],af[mt][3],
                      Ab + row*128 + ((ch ^ (row&7))<<4));
            }
            unsigned bfr[2][4];
            #pragma unroll
            for (int np=0; np<2; np++){
                int row = wn*32 + np*16 + (lane&7) + ((lane>=16)?8:0);
                int ch  = kk*2 + ((lane>>3)&1);
                ldsm4(bfr[np][0],bfr[np][1],bfr[np][2],bfr[np][3],
                      Bb + row*128 + ((ch ^ (row&7))<<4));
            }
            #pragma unroll
            for (int mt=0; mt<4; mt++)
                #pragma unroll
                for (int nt=0; nt<4; nt++)
                    mma16816(acc[mt][nt], af[mt], bfr[nt>>1][(nt&1)*2], bfr[nt>>1][(nt&1)*2+1]);
        }
        __syncthreads();
    }

    // epilogue
    const int r = lane>>2, cp2 = (lane&3)*2;
    #pragma unroll
    for (int mt=0; mt<4; mt++){
        #pragma unroll
        for (int nt=0; nt<4; nt++){
            int m = m0 + wm*64 + mt*16 + r;
            int n = n0 + wn*32 + nt*8 + cp2;
            int dir = n >> 11;
            int col = n & 2047;
            float2 bv = *(const float2*)(bias + n);
            float2 o0 = make_float2(acc[mt][nt][0]+bv.x, acc[mt][nt][1]+bv.y);
            float2 o1 = make_float2(acc[mt][nt][2]+bv.x, acc[mt][nt][3]+bv.y);
            *(float2*)&g_PRE[((size_t)dir*MM + m)*2048 + col]     = o0;
            *(float2*)&g_PRE[((size_t)dir*MM + m + 8)*2048 + col] = o1;
        }
    }
}

// ---------------- persistent LSTM scan with bf16 tensor cores ----------------
// 128 blocks (1/SM), 256 threads. Block: (dir, 8 hidden units j0..j0+7 -> 32 W rows).
// SMEM: Ws[32][512] bf16 (resident), Asm[128][512] bf16 (h_prev, restaged/step), zb[128][36] f32.
__global__ __launch_bounds__(256, 1) void lstm_scan_mma(int layer)
{
    extern __shared__ char smraw[];
    bf16* Ws  = (bf16*)smraw;                        // 32 KB
    bf16* Asm = (bf16*)(smraw + 32*1024);            // 128 KB
    float* zb = (float*)(smraw + 32*1024 + 128*1024);// [128][36] 18 KB

    bf16* Hbuf = layer ? g_HBb : g_HAb;
    const bf16* WH = layer ? g_WH1b : g_WH0b;
    const int bid = blockIdx.x;
    const int dir = bid >> 6;
    const int j0  = (bid & 63) << 3;
    const int tid = threadIdx.x;
    const int warp = tid>>5, lane = tid&31;
    const int wm = warp>>1, wn = warp&1;
    unsigned WsB = su32(Ws), AsB = su32(Asm);

    // ---- load Whh slice (32 rows x 512) once, swizzled ----
    {
        const bf16* wb = WH + (size_t)dir*2048*512;
        int rr = tid>>3;                  // 0..31
        int kc0 = (tid&7)*8;              // chunk base
        int wrow = ((rr>>3)<<9) + j0 + (rr&7);   // gate*512 + j
        const bf16* gp = wb + (size_t)wrow*512 + kc0*8;
        unsigned srw = WsB + rr*1024;
        #pragma unroll
        for (int i=0;i<8;i++){
            int kc = kc0+i;
            cp16(srw + ((kc ^ (rr&7))<<4), gp + i*8);
        }
        cpcommit(); cpwait<0>();
    }
    unsigned bar_target = *(volatile unsigned*)&g_bar_gen;
    __syncthreads();

    const int am = tid & 127;             // staging row (batch)
    const int ah = tid >> 7;              // 0/1 half
    unsigned AsRow = AsB + am*1024;

    for (int s=0; s<TT; s++){
        const int t_out = dir ? (TT-1-s) : s;
        float acc[2][2][4];
        #pragma unroll
        for (int i=0;i<2;i++)
            #pragma unroll
            for (int j=0;j<2;j++)
                #pragma unroll
                for (int k=0;k<4;k++) acc[i][j][k]=0.f;

        if (s > 0){
            const int t_prev = dir ? (t_out+1) : (s-1);
            const bf16* hb = Hbuf + ((size_t)t_prev*BB + am)*1024 + (dir<<9) + ah*256;
            #pragma unroll
            for (int i=0;i<32;i++){
                int kc = ah*32 + i;
                cp16(AsRow + ((kc ^ (am&7))<<4), hb + i*8);
            }
            cpcommit(); cpwait<0>();
            __syncthreads();

            #pragma unroll 4
            for (int kk=0; kk<32; kk++){
                unsigned af[2][4];
                #pragma unroll
                for (int mt=0; mt<2; mt++){
                    int row = wm*32 + mt*16 + (lane&7) + ((lane>>3)&1)*8;
                    int ch  = kk*2 + (lane>>4);
                    ldsm4(af[mt][0],af[mt][1],af[mt][2],af[mt][3],
                          AsB + row*1024 + ((ch ^ (row&7))<<4));
                }
                unsigned bfr[4];
                {
                    int row = wn*16 + (lane&7) + ((lane>=16)?8:0);
                    int ch  = kk*2 + ((lane>>3)&1);
                    ldsm4(bfr[0],bfr[1],bfr[2],bfr[3],
                          WsB + row*1024 + ((ch ^ (row&7))<<4));
                }
                #pragma unroll
                for (int mt=0; mt<2; mt++){
                    mma16816(acc[mt][0], af[mt], bfr[0], bfr[1]);
                    mma16816(acc[mt][1], af[mt], bfr[2], bfr[3]);
                }
            }
        }
        __syncthreads();
        // write z tile to smem
        {
            const int r = lane>>2, cp2 = (lane&3)*2;
            #pragma unroll
            for (int mt=0; mt<2; mt++)
                #pragma unroll
                for (int nt=0; nt<2; nt++){
                    int mr = wm*32 + mt*16 + r;
                    int nc = wn*16 + nt*8 + cp2;
                    zb[mr*36 + nc]       = acc[mt][nt][0];
                    zb[mr*36 + nc+1]     = acc[mt][nt][1];
                    zb[(mr+8)*36 + nc]   = acc[mt][nt][2];
                    zb[(mr+8)*36 + nc+1] = acc[mt][nt][3];
                }
        }
        __syncthreads();

        // gates + state update: 1024 cells = 128 b x 8 jj
        const float* prer = g_PRE + ((size_t)dir*MM + (size_t)t_out*BB)*2048;
        #pragma unroll
        for (int q=0;q<4;q++){
            int id = tid + (q<<8);
            int b = id>>3, jj = id&7;
            int j = j0 + jj;
            const float* pr = prer + (size_t)b*2048 + j;
            float zi = zb[b*36 + jj]      + pr[0];
            float zf = zb[b*36 + 8 + jj]  + pr[512];
            float zg = zb[b*36 + 16 + jj] + pr[1024];
            float zo = zb[b*36 + 24 + jj] + pr[1536];
            float* cpp = &g_C[((dir<<7)+b)*512 + j];
            float cprev = (s>0) ? *cpp : 0.f;
            float fi=sigf(zi), ff=sigf(zf), fg=tanhf(zg), fo=sigf(zo);
            float c = ff*cprev + fi*fg;
            float h = fo*tanhf(c);
            *cpp = c;
            Hbuf[((size_t)t_out*BB + b)*1024 + (dir<<9) + j] = __float2bfloat16(h);
        }

        bar_target++;
        grid_barrier(bar_target);
    }
}

// ---------------- classifier emissions (h in bf16) ----------------
__global__ void emissions_kernel(const float* __restrict__ clsW, const float* __restrict__ clsB)
{
    int warp = threadIdx.x >> 5, lane = threadIdx.x & 31;
    int row = (blockIdx.x << 3) + warp;
    const bf16* h = g_HBb + (size_t)row * 1024;
    float hv[32];
    #pragma unroll
    for (int m=0;m<32;m++) hv[m] = __bfloat162float(h[lane + (m<<5)]);
    #pragma unroll
    for (int c=0;c<CC;c++) {
        const float* w = clsW + c*1024;
        float s = 0.f;
        #pragma unroll
        for (int m=0;m<32;m++) s += hv[m]*w[lane + (m<<5)];
        #pragma unroll
        for (int o=16;o;o>>=1) s += __shfl_xor_sync(0xffffffffu, s, o);
        if (lane==0) g_EM[(size_t)row*CC + c] = s + clsB[c];
    }
}

// ---------------- CRF numerator ----------------
__global__ void crf_num_kernel(const int* __restrict__ y, const float* __restrict__ trans,
                               const float* __restrict__ cstart, const float* __restrict__ cend)
{
    int b = threadIdx.x;
    int y0 = y[b*TT];
    int tg = y0 > 0 ? y0 : 0;
    float sc = cstart[tg] + g_EM[(size_t)b*CC + tg];
    int cnt = (y0 > -1) ? 1 : 0;
    int prev = tg;
    for (int t=1;t<TT;t++) {
        int yt = y[b*TT + t];
        int tgt = yt > 0 ? yt : 0;
        float mf = (yt > -1) ? 1.f : 0.f;
        sc += (trans[prev*CC + tgt] + g_EM[((size_t)t*BB + b)*CC + tgt]) * mf;
        prev = tgt;
        cnt += (yt > -1) ? 1 : 0;
    }
    int se = cnt - 1; if (se < 0) se = 0;
    int yl = y[b*TT + se];
    int lt = yl > 0 ? yl : 0;
    sc += cend[lt];
    g_SC[b] = sc;
}

// ---------------- CRF denominator ----------------
__global__ void crf_den_kernel(const int* __restrict__ y, const float* __restrict__ trans,
                               const float* __restrict__ cstart, const float* __restrict__ cend)
{
    int b = (blockIdx.x << 3) + (threadIdx.x >> 5);
    int lane = threadIdx.x & 31;
    int c = lane < CC ? lane : CC-1;
    float tcol[CC];
    #pragma unroll
    for (int i=0;i<CC;i++) tcol[i] = trans[i*CC + c];
    float alpha = cstart[c] + g_EM[(size_t)b*CC + c];
    for (int t=1;t<TT;t++) {
        float e = g_EM[((size_t)t*BB + b)*CC + c];
        float av[CC]; float mx = -1e30f;
        #pragma unroll
        for (int i=0;i<CC;i++) { av[i] = __shfl_sync(0xffffffffu, alpha, i) + tcol[i]; mx = fmaxf(mx, av[i]); }
        float su = 0.f;
        #pragma unroll
        for (int i=0;i<CC;i++) su += expf(av[i]-mx);
        float nxt = mx + logf(su) + e;
        if (y[b*TT + t] > -1) alpha = nxt;
    }
    float v = alpha + cend[c];
    float mx = -1e30f;
    #pragma unroll
    for (int i=0;i<CC;i++) mx = fmaxf(mx, __shfl_sync(0xffffffffu, v, i));
    float su = 0.f;
    #pragma unroll
    for (int i=0;i<CC;i++) su += expf(__shfl_sync(0xffffffffu, v, i) - mx);
    if (lane==0) g_LLH[b] = g_SC[b] - (mx + logf(su));
}

// ---------------- final reduction ----------------
__global__ void final_kernel(float* __restrict__ out)
{
    int tid = threadIdx.x;
    float v = g_LLH[tid];
    #pragma unroll
    for (int o=16;o;o>>=1) v += __shfl_xor_sync(0xffffffffu, v, o);
    __shared__ float sr[4];
    if ((tid&31)==0) sr[tid>>5] = v;
    __syncthreads();
    if (tid==0) out[0] = -(sr[0]+sr[1]+sr[2]+sr[3]) / 128.0f;
}

// ---------------- launch ----------------
extern "C" void kernel_launch(void* const* d_in, const int* in_sizes, int n_in,
                              void* d_out, int out_size)
{
    const int*   x        = (const int*)  d_in[0];
    const int*   y        = (const int*)  d_in[1];
    const float* embed    = (const float*)d_in[2];
    const float* w_ih_l0  = (const float*)d_in[3];
    const float* w_hh_l0  = (const float*)d_in[4];
    const float* b_l0     = (const float*)d_in[5];
    const float* w_ih_l1  = (const float*)d_in[6];
    const float* w_hh_l1  = (const float*)d_in[7];
    const float* b_l1     = (const float*)d_in[8];
    const float* cls_w    = (const float*)d_in[9];
    const float* cls_b    = (const float*)d_in[10];
    const float* crf_start= (const float*)d_in[11];
    const float* crf_end  = (const float*)d_in[12];
    const float* crf_trans= (const float*)d_in[13];
    float* out = (float*)d_out;

    const int GEMM_SMEM = 2*(128*64)*2*2;                       // 65536 B
    const int SCAN_SMEM = 32*1024 + 128*1024 + 128*36*4;        // 182272 B
    cudaFuncSetAttribute(gemm_pre_mma, cudaFuncAttributeMaxDynamicSharedMemorySize, GEMM_SMEM);
    cudaFuncSetAttribute(lstm_scan_mma, cudaFuncAttributeMaxDynamicSharedMemorySize, SCAN_SMEM);

    embed_kernel<<<MM, 128>>>(x, embed);
    convert_weights<<<512, 256>>>(w_ih_l0, w_hh_l0, w_ih_l1, w_hh_l1);

    gemm_pre_mma<<<dim3(32,256), 256, GEMM_SMEM>>>(0, b_l0);
    lstm_scan_mma<<<128, 256, SCAN_SMEM>>>(0);
    gemm_pre_mma<<<dim3(32,256), 256, GEMM_SMEM>>>(1, b_l1);
    lstm_scan_mma<<<128, 256, SCAN_SMEM>>>(1);

    emissions_kernel<<<4096, 256>>>(cls_w, cls_b);
    crf_num_kernel<<<1, 128>>>(y, crf_trans, crf_start, crf_end);
    crf_den_kernel<<<16, 256>>>(y, crf_trans, crf_start, crf_end);
    final_kernel<<<1, 128>>>(out);
}